// round 12
// baseline (speedup 1.0000x reference)
#include <cuda_runtime.h>

// Router: logits = x @ wg^T + gr @ gm^T ; std-normalized softmax; top-2;
// mask expert E-1; renormalize.
// Output layout (float32): [gates 2T | indices 2T | logits 8T]
//
// R12: split-K / register-wg. R1-R11 all re-read wg from smem/L1 at
// 64KB per 8 tokens -> 18-22us of L1 work (the measured plateau).
// Here warp w owns k-chunks w*32+{s+8k}; lane (e4=lane&3, s=lane>>2)
// holds wg[e4][...] and wg[e4+4][...] in 32 REGISTERS (loaded once).
// x is read by direct LDG: op k = one 128B line, 4-way dedup'd.
// Partial sums (per warp, per token, 8 experts) combine via smem at
// the end. No smem staging, no cp.async, no mainloop barriers.

constexpr int D       = 2048;
constexpr int E       = 8;
constexpr int CH      = D / 4;        // 512 16B-chunks per row
constexpr int THREADS = 512;          // 16 warps = full K coverage
constexpr int WARPS   = 16;
constexpr int GRID    = 148;
constexpr int TOKMAX  = 112;          // max tokens per CTA (16384/148 -> 111)
constexpr int PSTRIDE = 136;          // partial row stride (bank-clean)

// smem floats: gm[64] | logitsb[TOKMAX*8] | partial[TOKMAX*PSTRIDE]
constexpr int GM_OFF   = 0;
constexpr int LB_OFF   = 64;
constexpr int PART_OFF = LB_OFF + TOKMAX * 8;
constexpr int SMEM_FLOATS = PART_OFF + TOKMAX * PSTRIDE;
constexpr int SMEM_BYTES  = SMEM_FLOATS * 4;    // ~65KB

__device__ __forceinline__ unsigned long long ffma2(unsigned long long a,
                                                    unsigned long long b,
                                                    unsigned long long c) {
    unsigned long long d;
    asm("fma.rn.f32x2 %0, %1, %2, %3;" : "=l"(d) : "l"(a), "l"(b), "l"(c));
    return d;
}

__device__ __forceinline__ float pairsum(unsigned long long v) {
    float2 f;
    f.x = __uint_as_float((unsigned int)(v & 0xffffffffull));
    f.y = __uint_as_float((unsigned int)(v >> 32));
    return f.x + f.y;
}

__device__ __forceinline__ ulonglong2 ldcs16(const ulonglong2* p) {
    ulonglong2 v;
    asm volatile("ld.global.cs.v2.u64 {%0, %1}, [%2];"
                 : "=l"(v.x), "=l"(v.y) : "l"(p));
    return v;
}

__global__ void __launch_bounds__(THREADS, 1)
router_kernel(const float* __restrict__ x,
              const float* __restrict__ wg,
              const float* __restrict__ gm,
              const float* __restrict__ gr,
              float* __restrict__ out_gates,
              float* __restrict__ out_idx,
              float* __restrict__ out_logits,
              int T) {
    extern __shared__ float smem[];
    float* s_gm   = smem + GM_OFF;
    float* s_lb   = smem + LB_OFF;
    float* s_part = smem + PART_OFF;

    const int tid  = threadIdx.x;
    const int lane = tid & 31;
    const int wid  = tid >> 5;        // 0..15: k-slice owner
    const int e4   = lane & 3;        // expert group (handles e4, e4+4)
    const int s    = lane >> 2;       // 0..7: k-sub within slice

    if (tid < E * E) s_gm[tid] = gm[tid];

    // ---- load this lane's wg slice into registers (once) ----
    // lane covers chunks w*32 + s + 8k (k=0..3) for experts e4 and e4+4
    const ulonglong2* w2 = reinterpret_cast<const ulonglong2*>(wg);
    ulonglong2 wr[2][4];
    #pragma unroll
    for (int p = 0; p < 2; p++)
        #pragma unroll
        for (int k = 0; k < 4; k++)
            wr[p][k] = w2[(size_t)(e4 + 4 * p) * CH + wid * 32 + 8 * k + s];

    // ---- token range for this CTA ----
    const int start = (int)(((long long)blockIdx.x * T) / GRID);
    const int end   = (int)(((long long)(blockIdx.x + 1) * T) / GRID);
    const int ntok  = end - start;

    const ulonglong2* xbase =
        reinterpret_cast<const ulonglong2*>(x) + (size_t)start * CH + wid * 32;

    // ---- mainloop: every warp processes every CTA token on its k-slice ----
    #pragma unroll 2
    for (int tt = 0; tt < ntok; tt++) {
        const ulonglong2* xr = xbase + (size_t)tt * CH;
        // op k: lanes read chunks 8k..8k+7 (s across lanes) = one 128B
        // line, 4-way dedup over e4 -> 1 wavefront each
        ulonglong2 xv0 = ldcs16(xr + 0 + s);
        ulonglong2 xv1 = ldcs16(xr + 8 + s);
        ulonglong2 xv2 = ldcs16(xr + 16 + s);
        ulonglong2 xv3 = ldcs16(xr + 24 + s);

        unsigned long long a0 = 0ull, a1 = 0ull;
        a0 = ffma2(xv0.x, wr[0][0].x, a0); a0 = ffma2(xv0.y, wr[0][0].y, a0);
        a0 = ffma2(xv1.x, wr[0][1].x, a0); a0 = ffma2(xv1.y, wr[0][1].y, a0);
        a0 = ffma2(xv2.x, wr[0][2].x, a0); a0 = ffma2(xv2.y, wr[0][2].y, a0);
        a0 = ffma2(xv3.x, wr[0][3].x, a0); a0 = ffma2(xv3.y, wr[0][3].y, a0);
        a1 = ffma2(xv0.x, wr[1][0].x, a1); a1 = ffma2(xv0.y, wr[1][0].y, a1);
        a1 = ffma2(xv1.x, wr[1][1].x, a1); a1 = ffma2(xv1.y, wr[1][1].y, a1);
        a1 = ffma2(xv2.x, wr[1][2].x, a1); a1 = ffma2(xv2.y, wr[1][2].y, a1);
        a1 = ffma2(xv3.x, wr[1][3].x, a1); a1 = ffma2(xv3.y, wr[1][3].y, a1);

        float f0 = pairsum(a0);
        float f1 = pairsum(a1);
        // reduce over s (lane bits 2-4)
        f0 += __shfl_xor_sync(0xffffffffu, f0, 4);
        f1 += __shfl_xor_sync(0xffffffffu, f1, 4);
        f0 += __shfl_xor_sync(0xffffffffu, f0, 8);
        f1 += __shfl_xor_sync(0xffffffffu, f1, 8);
        f0 += __shfl_xor_sync(0xffffffffu, f0, 16);
        f1 += __shfl_xor_sync(0xffffffffu, f1, 16);

        if (s == 0) {
            s_part[tt * PSTRIDE + wid * 8 + e4]     = f0;
            s_part[tt * PSTRIDE + wid * 8 + e4 + 4] = f1;
        }
    }

    __syncthreads();

    // ---- combine the 16 warp-partials per (token, expert) ----
    for (int idx = tid; idx < ntok * 8; idx += THREADS) {
        const int tok = idx >> 3;
        const int e   = idx & 7;
        float sum = 0.f;
        #pragma unroll
        for (int w = 0; w < WARPS; w++)
            sum += s_part[tok * PSTRIDE + w * 8 + e];
        s_lb[tok * 8 + e] = sum;
    }

    __syncthreads();

    // ---- per-token epilogue ----
    for (int tok = tid; tok < ntok; tok += THREADS) {
        const int t = start + tok;

        float4 g0 = __ldg(reinterpret_cast<const float4*>(gr + (size_t)t * E));
        float4 g1 = __ldg(reinterpret_cast<const float4*>(gr + (size_t)t * E + 4));
        float grv[8] = {g0.x, g0.y, g0.z, g0.w, g1.x, g1.y, g1.z, g1.w};

        float lg[E];
        #pragma unroll
        for (int f = 0; f < E; f++) {
            float sv = s_lb[tok * 8 + f];
            #pragma unroll
            for (int e = 0; e < E; e++) sv = fmaf(grv[e], s_gm[f * E + e], sv);
            lg[f] = sv;
        }

        // unbiased std (ddof=1) over E=8
        float mean = 0.f;
        #pragma unroll
        for (int f = 0; f < E; f++) mean += lg[f];
        mean *= (1.f / E);
        float var = 0.f;
        #pragma unroll
        for (int f = 0; f < E; f++) {
            float d = lg[f] - mean;
            var = fmaf(d, d, var);
        }
        float inv_std = rsqrtf(var * (1.f / (E - 1)));

        float z[E], m = -3.402823466e+38f;
        #pragma unroll
        for (int f = 0; f < E; f++) {
            z[f] = lg[f] * inv_std;
            m = fmaxf(m, z[f]);
        }
        float p[E], psum = 0.f;
        #pragma unroll
        for (int f = 0; f < E; f++) {
            p[f] = __expf(z[f] - m);
            psum += p[f];
        }
        float inv_psum = 1.f / psum;
        #pragma unroll
        for (int f = 0; f < E; f++) p[f] *= inv_psum;

        // stable top-2 (descending, lower index wins ties)
        int i1 = 0; float v1 = p[0];
        #pragma unroll
        for (int f = 1; f < E; f++)
            if (p[f] > v1) { v1 = p[f]; i1 = f; }
        int i2; float v2;
        if (i1 == 0) { i2 = 1; v2 = p[1]; } else { i2 = 0; v2 = p[0]; }
        #pragma unroll
        for (int f = 1; f < E; f++)
            if (f != i1 && p[f] > v2) { v2 = p[f]; i2 = f; }

        float gg1 = (i1 == E - 1) ? 0.f : v1;
        float gg2 = (i2 == E - 1) ? 0.f : v2;
        float inv_s = 1.f / (gg1 + gg2);
        gg1 *= inv_s; gg2 *= inv_s;

        float2 gpair; gpair.x = gg1; gpair.y = gg2;
        *reinterpret_cast<float2*>(out_gates + (size_t)2 * t) = gpair;
        float2 ipair; ipair.x = (float)i1; ipair.y = (float)i2;
        *reinterpret_cast<float2*>(out_idx + (size_t)2 * t) = ipair;

        float4 L0; L0.x = lg[0]; L0.y = lg[1]; L0.z = lg[2]; L0.w = lg[3];
        float4 L1; L1.x = lg[4]; L1.y = lg[5]; L1.z = lg[6]; L1.w = lg[7];
        float4* olr = reinterpret_cast<float4*>(out_logits + (size_t)t * E);
        olr[0] = L0;
        olr[1] = L1;
    }
}

extern "C" void kernel_launch(void* const* d_in, const int* in_sizes, int n_in,
                              void* d_out, int out_size) {
    const float* x  = (const float*)d_in[0];   // [T, D]
    const float* wg = (const float*)d_in[1];   // [E, D]
    const float* gm = (const float*)d_in[2];   // [E, E]
    const float* gr = (const float*)d_in[3];   // [T, E]

    const int T = in_sizes[0] / D;
    float* out       = (float*)d_out;
    float* out_gates = out;                       // [T,2]
    float* out_idx   = out + (size_t)2 * T;       // [T,2] as float
    float* out_logit = out + (size_t)4 * T;       // [T,8]

    cudaFuncSetAttribute(router_kernel,
                         cudaFuncAttributeMaxDynamicSharedMemorySize,
                         SMEM_BYTES);

    router_kernel<<<GRID, THREADS, SMEM_BYTES>>>(x, wg, gm, gr,
                                                 out_gates, out_idx, out_logit,
                                                 T);
}

// round 13
// speedup vs baseline: 1.4607x; 1.4607x over previous
#include <cuda_runtime.h>

// Router: logits = x @ wg^T + gr @ gm^T ; std-normalized softmax; top-2;
// mask expert E-1; renormalize.
// Output layout (float32): [gates 2T | indices 2T | logits 8T]
//
// R13 = R7 (best: 33.5us) with the pipeline lead fixed. R7's DEPTH=2
// 4KB stages gave only ~1 iteration (~580cy) of cp.async lead --
// marginal vs ~600cy DRAM latency, so every wait_group stalled.
// Here: DEPTH=4 ring of 2KB half-stages (same 8KB/warp footprint),
// lead = 3 half-iters (~900cy). No register snapshot (R10's mistake):
// reads consume directly from smem, refill issued AFTER the reads.

constexpr int D       = 2048;
constexpr int E       = 8;
constexpr int NT      = 8;            // tokens per warp
constexpr int THREADS = 448;          // 14 warps, 1 CTA/SM
constexpr int WARPS   = THREADS / 32;
constexpr int CHUNKS  = D / 4;        // 16B chunks per row = 512
constexpr int STAGES  = 32;           // 2KB half-stages (16 chunks/token each)
constexpr int DEPTH   = 4;            // ring depth
constexpr int GRID    = 148;

// smem floats: wg [E*D] | gm [64] | ring [WARPS*DEPTH*512]
constexpr int XOFF_FLOATS = E * D + 64;                       // 16448
constexpr int RING_FLOATS = WARPS * DEPTH * 512;              // 28672
constexpr int SMEM_BYTES  = (XOFF_FLOATS + RING_FLOATS) * 4;  // 180480 B

__device__ __forceinline__ unsigned long long ffma2(unsigned long long a,
                                                    unsigned long long b,
                                                    unsigned long long c) {
    unsigned long long d;
    asm("fma.rn.f32x2 %0, %1, %2, %3;" : "=l"(d) : "l"(a), "l"(b), "l"(c));
    return d;
}

__device__ __forceinline__ float pairsum(unsigned long long v) {
    float2 f;
    f.x = __uint_as_float((unsigned int)(v & 0xffffffffull));
    f.y = __uint_as_float((unsigned int)(v >> 32));
    return f.x + f.y;
}

__device__ __forceinline__ void cp16(unsigned int dst_smem, const void* src) {
    asm volatile("cp.async.cg.shared.global [%0], [%1], 16;\n"
                 :: "r"(dst_smem), "l"(src) : "memory");
}

__global__ void __launch_bounds__(THREADS, 1)
router_kernel(const float* __restrict__ x,
              const float* __restrict__ wg,
              const float* __restrict__ gm,
              const float* __restrict__ gr,
              float* __restrict__ out_gates,
              float* __restrict__ out_idx,
              float* __restrict__ out_logits,
              int nGroups) {
    extern __shared__ float smem[];
    float4* s_wg4 = reinterpret_cast<float4*>(smem);            // [E][D]
    float*  s_gm  = smem + E * D;                               // [E][E]

    const float4* wg4 = reinterpret_cast<const float4*>(wg);
    for (int i = threadIdx.x; i < E * CHUNKS; i += THREADS) s_wg4[i] = wg4[i];
    if (threadIdx.x < E * E) s_gm[threadIdx.x] = gm[threadIdx.x];
    __syncthreads();

    const ulonglong2* s_w2 = reinterpret_cast<const ulonglong2*>(smem);

    const int lane  = threadIdx.x & 31;
    const int wid   = threadIdx.x >> 5;
    const int l8    = lane & 7;         // position within octet
    const int e0    = (lane >> 3) * 2;  // this octet's first expert
    const int tcp   = lane >> 2;        // 0..7: token this lane copies
    const int c4    = lane & 3;         // 0..3: chunk-subindex this lane copies

    // Per-warp ring: DEPTH half-stages of 2KB (8 tokens x 16 chunks x 16B).
    float* ring = smem + XOFF_FLOATS + wid * (DEPTH * 512);
    const unsigned int ring_addr = (unsigned int)__cvta_generic_to_shared(ring);
    const ulonglong2* ring_u2 = reinterpret_cast<const ulonglong2*>(ring);

    const int g = blockIdx.x + gridDim.x * wid;   // one unit per warp

    if (g < nGroups) {
        const int t0 = g * NT;
        const char* xrow = reinterpret_cast<const char*>(x + (size_t)t0 * D);
        // half-stage s covers chunks s*16 .. s*16+15 of every token.
        // copy op o (0..3): lane copies token tcp, chunk s*16 + c4 + 4o.

        unsigned long long acc[NT][2];
        #pragma unroll
        for (int j = 0; j < NT; j++) { acc[j][0] = 0ull; acc[j][1] = 0ull; }

        // ---- prologue: half-stages 0..DEPTH-1 ----
        #pragma unroll
        for (int s = 0; s < DEPTH; s++) {
            #pragma unroll
            for (int o = 0; o < 4; o++) {
                cp16(ring_addr + s * 2048 + tcp * 256 + (c4 + 4 * o) * 16,
                     xrow + (size_t)tcp * (D * 4) + (s * 16 + c4 + 4 * o) * 16);
            }
            asm volatile("cp.async.commit_group;\n" ::: "memory");
        }

        #pragma unroll 4
        for (int hh = 0; hh < STAGES; hh++) {
            // committed = DEPTH + hh; pending <= DEPTH-1 => stage hh landed
            asm volatile("cp.async.wait_group %0;\n" :: "n"(DEPTH - 1) : "memory");

            const int slot = hh & (DEPTH - 1);
            const ulonglong2* xs = ring_u2 + slot * 128;  // 2048B / 16

            #pragma unroll
            for (int k2 = 0; k2 < 2; k2++) {
                const int c = hh * 16 + k2 * 8 + l8;
                ulonglong2 wv0 = s_w2[e0 * CHUNKS + c];
                ulonglong2 wv1 = s_w2[(e0 + 1) * CHUNKS + c];
                #pragma unroll
                for (int j = 0; j < NT; j++) {
                    ulonglong2 xv = xs[j * 16 + k2 * 8 + l8];
                    acc[j][0] = ffma2(xv.x, wv0.x, acc[j][0]);
                    acc[j][0] = ffma2(xv.y, wv0.y, acc[j][0]);
                    acc[j][1] = ffma2(xv.x, wv1.x, acc[j][1]);
                    acc[j][1] = ffma2(xv.y, wv1.y, acc[j][1]);
                }
            }

            // refill slot with half-stage hh+DEPTH — strictly AFTER the
            // reads above (slot consumed again only at iter hh+DEPTH).
            const int s = hh + DEPTH;
            if (s < STAGES) {
                #pragma unroll
                for (int o = 0; o < 4; o++) {
                    cp16(ring_addr + slot * 2048 + tcp * 256 + (c4 + 4 * o) * 16,
                         xrow + (size_t)tcp * (D * 4) + (s * 16 + c4 + 4 * o) * 16);
                }
            }
            asm volatile("cp.async.commit_group;\n" ::: "memory");
        }

        // ---- reduce within each octet (3-step butterfly) ----
        float red[NT][2];
        #pragma unroll
        for (int j = 0; j < NT; j++) {
            #pragma unroll
            for (int e = 0; e < 2; e++) {
                float s = pairsum(acc[j][e]);
                s += __shfl_xor_sync(0xffffffffu, s, 4);
                s += __shfl_xor_sync(0xffffffffu, s, 2);
                s += __shfl_xor_sync(0xffffffffu, s, 1);
                red[j][e] = s;
            }
        }

        // lane (octet q, l8=j) keeps token t0+j's logits for experts
        // 2q, 2q+1; gather all 8 experts onto lanes 0-7.
        float s0 = red[0][0], s1 = red[0][1];
        #pragma unroll
        for (int jj = 1; jj < NT; jj++)
            if (l8 == jj) { s0 = red[jj][0]; s1 = red[jj][1]; }

        float logit[E];
        logit[0] = s0;
        logit[1] = s1;
        logit[2] = __shfl_sync(0xffffffffu, s0, l8 + 8);
        logit[3] = __shfl_sync(0xffffffffu, s1, l8 + 8);
        logit[4] = __shfl_sync(0xffffffffu, s0, l8 + 16);
        logit[5] = __shfl_sync(0xffffffffu, s1, l8 + 16);
        logit[6] = __shfl_sync(0xffffffffu, s0, l8 + 24);
        logit[7] = __shfl_sync(0xffffffffu, s1, l8 + 24);

        if (lane < NT) {
            const int t = t0 + lane;

            float4 g0 = __ldg(reinterpret_cast<const float4*>(gr + (size_t)t * E));
            float4 g1 = __ldg(reinterpret_cast<const float4*>(gr + (size_t)t * E + 4));
            float grv[8] = {g0.x, g0.y, g0.z, g0.w, g1.x, g1.y, g1.z, g1.w};
            float lg[E];
            #pragma unroll
            for (int f = 0; f < E; f++) {
                float s = logit[f];
                #pragma unroll
                for (int e = 0; e < E; e++) s = fmaf(grv[e], s_gm[f * E + e], s);
                lg[f] = s;
            }

            // unbiased std (ddof=1) over E=8
            float mean = 0.f;
            #pragma unroll
            for (int f = 0; f < E; f++) mean += lg[f];
            mean *= (1.f / E);
            float var = 0.f;
            #pragma unroll
            for (int f = 0; f < E; f++) {
                float d = lg[f] - mean;
                var = fmaf(d, d, var);
            }
            float inv_std = rsqrtf(var * (1.f / (E - 1)));

            float z[E], m = -3.402823466e+38f;
            #pragma unroll
            for (int f = 0; f < E; f++) {
                z[f] = lg[f] * inv_std;
                m = fmaxf(m, z[f]);
            }
            float p[E], psum = 0.f;
            #pragma unroll
            for (int f = 0; f < E; f++) {
                p[f] = __expf(z[f] - m);
                psum += p[f];
            }
            float inv_psum = 1.f / psum;
            #pragma unroll
            for (int f = 0; f < E; f++) p[f] *= inv_psum;

            // stable top-2 (descending, lower index wins ties)
            int i1 = 0; float v1 = p[0];
            #pragma unroll
            for (int f = 1; f < E; f++)
                if (p[f] > v1) { v1 = p[f]; i1 = f; }
            int i2; float v2;
            if (i1 == 0) { i2 = 1; v2 = p[1]; } else { i2 = 0; v2 = p[0]; }
            #pragma unroll
            for (int f = 1; f < E; f++)
                if (f != i1 && p[f] > v2) { v2 = p[f]; i2 = f; }

            float gg1 = (i1 == E - 1) ? 0.f : v1;
            float gg2 = (i2 == E - 1) ? 0.f : v2;
            float inv_s = 1.f / (gg1 + gg2);
            gg1 *= inv_s; gg2 *= inv_s;

            float2 gpair; gpair.x = gg1; gpair.y = gg2;
            *reinterpret_cast<float2*>(out_gates + (size_t)2 * t) = gpair;
            float2 ipair; ipair.x = (float)i1; ipair.y = (float)i2;
            *reinterpret_cast<float2*>(out_idx + (size_t)2 * t) = ipair;

            float4 L0; L0.x = lg[0]; L0.y = lg[1]; L0.z = lg[2]; L0.w = lg[3];
            float4 L1; L1.x = lg[4]; L1.y = lg[5]; L1.z = lg[6]; L1.w = lg[7];
            float4* olr = reinterpret_cast<float4*>(out_logits + (size_t)t * E);
            olr[0] = L0;
            olr[1] = L1;
        }

        asm volatile("cp.async.wait_group 0;\n" ::: "memory");
    }
}

extern "C" void kernel_launch(void* const* d_in, const int* in_sizes, int n_in,
                              void* d_out, int out_size) {
    const float* x  = (const float*)d_in[0];   // [T, D]
    const float* wg = (const float*)d_in[1];   // [E, D]
    const float* gm = (const float*)d_in[2];   // [E, E]
    const float* gr = (const float*)d_in[3];   // [T, E]

    const int T = in_sizes[0] / D;
    float* out       = (float*)d_out;
    float* out_gates = out;                       // [T,2]
    float* out_idx   = out + (size_t)2 * T;       // [T,2] as float
    float* out_logit = out + (size_t)4 * T;       // [T,8]

    cudaFuncSetAttribute(router_kernel,
                         cudaFuncAttributeMaxDynamicSharedMemorySize,
                         SMEM_BYTES);

    const int nGroups = T / NT;                   // 2048
    router_kernel<<<GRID, THREADS, SMEM_BYTES>>>(x, wg, gm, gr,
                                                 out_gates, out_idx, out_logit,
                                                 nGroups);
}